// round 13
// baseline (speedup 1.0000x reference)
#include <cuda_runtime.h>
#include <cstdint>

// NMS_20933670600803  — heatmap (B,1,14,14) f32 -> [m1 | m2] f32
//
// R13 = R12 (half-warp items) + occupancy restoration + L2-persist input.
//  - __launch_bounds__(256, 6): caps regs at 42 -> 6 blocks/SM (75% occ),
//    up from 44 regs / 5 blocks (52%). R12's instruction count is the lowest
//    of all variants (~175/item); it was purely occupancy-starved.
//  - input loads use default cache policy (input is L2-resident across graph
//    replays; __ldcs was marking it evict-first). Output keeps __stcs.
//
// Each 16-lane half owns one batch item; one instruction stream serves two:
//  - __reduce_max_sync with disjoint half masks = both argmaxes in one REDUX
//  - one table LDG.128/iter covers both items
//  - all post-loop scalar work per-lane, shared across items.
//
// Keys (validated R4-R12, rel_err 0):
//   key = (max(fb, bits(0.6f)) << 8) + (0xE66666FF - i)  [mod 2^32]
// unsigned max == jnp.argmax (max value, tie -> smallest index).
// Dead slots (i >= 196) collapse to 255-i <= 59 < 60 <= live keys.

#define NPIX 196
#define NVEC 49
#define WPB  8
#define THREADS (WPB * 32)
#define KTHR   0x3F19999Au      // __float_as_uint(0.6f)
#define MUL14  306790400u       // 18725 << 14 ; umulhi(i, MUL14) = i/14 (i<256)

struct alignas(16) HalfTable {
    // w[bi][q] : uint4; bytes = 0xFF if element suppressed by peak bi else 0
    //   word0 byte c -> elem 4q+c ; word1 -> 64+4q+c ; word2 -> 128+4q+c
    //   word3 byte0  -> elem 192+q (only q<4 meaningful)
    unsigned w[196][16][4];
    constexpr HalfTable() : w{} {
        for (int bi = 0; bi < 196; ++bi) {
            const int x = bi / 14, y = bi % 14;
            const int x1 = (x - 5 > 0) ? x - 5 : 0;
            const int x2 = (x + 5 < 15) ? x + 5 : 15;
            const int y1 = (y - 5 > 0) ? y - 5 : 0;
            const int y2 = (y + 5 < 15) ? y + 5 : 15;
            for (int q = 0; q < 16; ++q) {
                for (int s = 0; s < 3; ++s) {
                    unsigned word = 0;
                    for (int c = 0; c < 4; ++c) {
                        const int i = 4 * q + 64 * s + c;
                        const int eu = i / 14, ev = i % 14;
                        if (eu >= x1 && eu < x2 && ev >= y1 && ev < y2)
                            word |= 0xFFu << (8 * c);
                    }
                    w[bi][q][s] = word;
                }
                unsigned w3 = 0;
                if (q < 4) {
                    const int i = 192 + q;
                    const int eu = i / 14, ev = i % 14;
                    if (eu >= x1 && eu < x2 && ev >= y1 && ev < y2)
                        w3 = 0xFFu;
                }
                w[bi][q][3] = w3;
            }
        }
    }
};
__device__ const HalfTable g_tbl;    // 50176 B global, constexpr-initialized

__global__ __launch_bounds__(THREADS, 6)
void nms_masks_kernel(const float4* __restrict__ hm,
                      float4* __restrict__ out,
                      int B)
{
    const int warp = blockIdx.x * WPB + (threadIdx.x >> 5);
    const int lane = threadIdx.x & 31;
    const int q    = lane & 15;               // lane within half
    const int h    = lane >> 4;               // half index: 0 or 1
    const int item = 2 * warp + h;
    if (item >= B) return;

    const unsigned gmask = 0xFFFFu << (16 * h);   // this half's REDUX mask

    const float4* __restrict__ p = hm + (size_t)item * NVEC;
    const float4 f0 = __ldg(p + q);               // elems 4q   .. 4q+3
    const float4 f1 = __ldg(p + q + 16);          // elems 64+4q..
    const float4 f2 = __ldg(p + q + 32);          // elems 128+4q..
    float e3 = 0.0f;                              // elem 192+q (q<4)
    if (q < 4) e3 = __ldg(reinterpret_cast<const float*>(p) + 192 + q);

    // ---- keys ----
    unsigned key[13];
    {
        const float vals[12] = {f0.x, f0.y, f0.z, f0.w,
                                f1.x, f1.y, f1.z, f1.w,
                                f2.x, f2.y, f2.z, f2.w};
        const unsigned base = 0xE66666FFu - 4u * (unsigned)q;
#pragma unroll
        for (int c = 0; c < 12; ++c) {
            const unsigned fb = __float_as_uint(vals[c]);
            const unsigned M  = (fb > KTHR) ? fb : KTHR;              // IMNMX.U32
            key[c] = M * 256u + (base - (unsigned)(64 * (c >> 2) + (c & 3)));
        }
        // elem 192+q ; for q>=4 e3=0 -> key = 255-(192+q) <= 59, never wins
        const unsigned fb = __float_as_uint(e3);
        const unsigned M  = (fb > KTHR) ? fb : KTHR;
        key[12] = M * 256u + (0xE66666FFu - (unsigned)(192 + q));
    }

    int bis[4];
#pragma unroll
    for (int it = 0; it < 4; ++it) {
        // local max over 13 keys (12 IMNMX)
        unsigned m = max(key[0], key[1]);
        m = max(m, max(key[2],  key[3]));
        m = max(m, max(key[4],  key[5]));
        m = max(m, max(key[6],  key[7]));
        m = max(m, max(key[8],  key[9]));
        m = max(m, max(key[10], key[11]));
        m = max(m, key[12]);

        // one REDUX serves both halves (disjoint masks)
        const unsigned w = __reduce_max_sync(gmask, m);
        const int bi = (int)((~w) & 0xFFu);
        bis[it] = bi;

        if (it < 3) {
            const uint4 t = __ldg(reinterpret_cast<const uint4*>(g_tbl.w[bi][q]));
            const unsigned tw[3] = {t.x, t.y, t.z};
#pragma unroll
            for (int s = 0; s < 3; ++s)
#pragma unroll
                for (int c = 0; c < 4; ++c) {
                    const unsigned mm = __byte_perm(tw[s], 0u, 0x1111 * c);
                    key[4 * s + c] &= (~mm | 0xFFu);   // single LOP3
                }
            const unsigned m12 = __byte_perm(t.w, 0u, 0x0000);
            key[12] &= (~m12 | 0xFFu);
        }
    }

    // ---- per-half scalar tail (computed once per lane, covers its item) ----
    int px[4], py[4], pk[4];
#pragma unroll
    for (int t = 0; t < 4; ++t) {
        const int x = (int)__umulhi((unsigned)bis[t], MUL14);     // bi / 14
        const int y = bis[t] - 14 * x;
        px[t] = x; py[t] = y; pk[t] = x | (y << 4);
    }

    unsigned kbest = 0;
    {
        const int pa[6] = {0, 0, 0, 1, 1, 2};
        const int pb[6] = {1, 2, 3, 2, 3, 3};
#pragma unroll
        for (int qq = 0; qq < 6; ++qq) {
            const int dx = px[pb[qq]] - px[pa[qq]];
            const int dy = py[pb[qq]] - py[pa[qq]];
            const int d  = dx * dx + dy * dy;       // <= 338
            const unsigned kd = ((unsigned)d << 20) | ((unsigned)(5 - qq) << 16)
                              | (unsigned)(pk[pa[qq]] | (pk[pb[qq]] << 8));
            kbest = (kbest > kd) ? kbest : kd;
        }
    }
    const int ax = (int)(kbest & 0xFu);
    const int ay = (int)((kbest >> 4)  & 0xFu);
    const int bx = (int)((kbest >> 8)  & 0xFu);
    const int by = (int)((kbest >> 12) & 0xFu);

    // d1 - d2 = Cy*i + Cg*eu + mCc   (ev = i - 14*eu folded in)
    const int dxc = bx - ax, dyc = by - ay;
    const int Cy  = 2 * dyc;
    const int Cg  = 2 * dxc - 14 * Cy;
    const int mCc = -(dxc * (ax + bx) + dyc * (ay + by));

    float4* __restrict__ o1 = out + (size_t)item * NVEC;
    float4* __restrict__ o2 = o1 + (size_t)B * NVEC;

#pragma unroll
    for (int s = 0; s < 3; ++s) {
        float r1[4], r2[4];
#pragma unroll
        for (int c = 0; c < 4; ++c) {
            const int i  = 4 * q + 64 * s + c;
            const int eu = (int)__umulhi((unsigned)i, MUL14);        // i / 14
            const int pv = Cy * i + (Cg * eu + mCc);                 // 2x IMAD
            const unsigned m1b = ((unsigned)pv >> 31) * 0x3F800000u; // SHF + IMAD
            r1[c] = __uint_as_float(m1b);       // 1.0f if d1<d2 else 0.0f
            r2[c] = 1.0f - r1[c];               // FADD, exact on {0,1}
        }
        __stcs(o1 + q + 16 * s, make_float4(r1[0], r1[1], r1[2], r1[3]));
        __stcs(o2 + q + 16 * s, make_float4(r2[0], r2[1], r2[2], r2[3]));
    }
    if (q < 4) {                                 // elems 192..195, scalar
        const int i  = 192 + q;                  // eu = 13
        const int pv = Cy * i + (Cg * 13 + mCc);
        const unsigned m1b = ((unsigned)pv >> 31) * 0x3F800000u;
        const float r1 = __uint_as_float(m1b);
        __stcs(reinterpret_cast<float*>(o1) + i, r1);
        __stcs(reinterpret_cast<float*>(o2) + i, 1.0f - r1);
    }
}

extern "C" void kernel_launch(void* const* d_in, const int* in_sizes, int n_in,
                              void* d_out, int out_size)
{
    const float4* hm  = (const float4*)d_in[0];
    float4*       out = (float4*)d_out;
    const int B = in_sizes[0] / NPIX;              // 131072
    const int nwarps = (B + 1) / 2;                // 2 items per warp
    const int grid = (nwarps + WPB - 1) / WPB;     // 8192
    nms_masks_kernel<<<grid, THREADS>>>(hm, out, B);
}

// round 14
// speedup vs baseline: 1.0194x; 1.0194x over previous
#include <cuda_runtime.h>
#include <cstdint>

// NMS_20933670600803  — heatmap (B,1,14,14) f32 -> [m1 | m2] f32
//
// R14 = R13 (half-warp items, launch_bounds(256,6)) + WRITE-THROUGH output.
// ncu R13: 249MB DRAM traffic vs 206MB mandatory writes -> ~43MB of input
// re-read because allocating output writes evict input from L2. __stwt gives
// the never-re-read output zero L2 footprint; the 103MB input then stays
// L2-resident across graph replays.
//
// Each 16-lane half owns one batch item; one instruction stream serves two:
//  - __reduce_max_sync with disjoint half masks = both argmaxes in one REDUX
//  - one table LDG.128/iter covers both items
//  - post-loop scalar work per-lane, shared across items.
//
// Keys (validated R4-R13, rel_err 0):
//   key = (max(fb, bits(0.6f)) << 8) + (0xE66666FF - i)  [mod 2^32]
// unsigned max == jnp.argmax (max value, tie -> smallest index).
// Dead slots (i >= 196) collapse to 255-i <= 59 < 60 <= live keys.

#define NPIX 196
#define NVEC 49
#define WPB  8
#define THREADS (WPB * 32)
#define KTHR   0x3F19999Au      // __float_as_uint(0.6f)
#define MUL14  306790400u       // 18725 << 14 ; umulhi(i, MUL14) = i/14 (i<256)

struct alignas(16) HalfTable {
    // w[bi][q] : uint4; bytes = 0xFF if element suppressed by peak bi else 0
    //   word0 byte c -> elem 4q+c ; word1 -> 64+4q+c ; word2 -> 128+4q+c
    //   word3 byte0  -> elem 192+q (only q<4 meaningful)
    unsigned w[196][16][4];
    constexpr HalfTable() : w{} {
        for (int bi = 0; bi < 196; ++bi) {
            const int x = bi / 14, y = bi % 14;
            const int x1 = (x - 5 > 0) ? x - 5 : 0;
            const int x2 = (x + 5 < 15) ? x + 5 : 15;
            const int y1 = (y - 5 > 0) ? y - 5 : 0;
            const int y2 = (y + 5 < 15) ? y + 5 : 15;
            for (int q = 0; q < 16; ++q) {
                for (int s = 0; s < 3; ++s) {
                    unsigned word = 0;
                    for (int c = 0; c < 4; ++c) {
                        const int i = 4 * q + 64 * s + c;
                        const int eu = i / 14, ev = i % 14;
                        if (eu >= x1 && eu < x2 && ev >= y1 && ev < y2)
                            word |= 0xFFu << (8 * c);
                    }
                    w[bi][q][s] = word;
                }
                unsigned w3 = 0;
                if (q < 4) {
                    const int i = 192 + q;
                    const int eu = i / 14, ev = i % 14;
                    if (eu >= x1 && eu < x2 && ev >= y1 && ev < y2)
                        w3 = 0xFFu;
                }
                w[bi][q][3] = w3;
            }
        }
    }
};
__device__ const HalfTable g_tbl;    // 50176 B global, constexpr-initialized

__global__ __launch_bounds__(THREADS, 6)
void nms_masks_kernel(const float4* __restrict__ hm,
                      float4* __restrict__ out,
                      int B)
{
    const int warp = blockIdx.x * WPB + (threadIdx.x >> 5);
    const int lane = threadIdx.x & 31;
    const int q    = lane & 15;               // lane within half
    const int h    = lane >> 4;               // half index: 0 or 1
    const int item = 2 * warp + h;
    if (item >= B) return;

    const unsigned gmask = 0xFFFFu << (16 * h);   // this half's REDUX mask

    const float4* __restrict__ p = hm + (size_t)item * NVEC;
    const float4 f0 = __ldg(p + q);               // elems 4q   .. 4q+3
    const float4 f1 = __ldg(p + q + 16);          // elems 64+4q..
    const float4 f2 = __ldg(p + q + 32);          // elems 128+4q..
    float e3 = 0.0f;                              // elem 192+q (q<4)
    if (q < 4) e3 = __ldg(reinterpret_cast<const float*>(p) + 192 + q);

    // ---- keys ----
    unsigned key[13];
    {
        const float vals[12] = {f0.x, f0.y, f0.z, f0.w,
                                f1.x, f1.y, f1.z, f1.w,
                                f2.x, f2.y, f2.z, f2.w};
        const unsigned base = 0xE66666FFu - 4u * (unsigned)q;
#pragma unroll
        for (int c = 0; c < 12; ++c) {
            const unsigned fb = __float_as_uint(vals[c]);
            const unsigned M  = (fb > KTHR) ? fb : KTHR;              // IMNMX.U32
            key[c] = M * 256u + (base - (unsigned)(64 * (c >> 2) + (c & 3)));
        }
        // elem 192+q ; for q>=4 e3=0 -> key = 255-(192+q) <= 59, never wins
        const unsigned fb = __float_as_uint(e3);
        const unsigned M  = (fb > KTHR) ? fb : KTHR;
        key[12] = M * 256u + (0xE66666FFu - (unsigned)(192 + q));
    }

    int bis[4];
#pragma unroll
    for (int it = 0; it < 4; ++it) {
        // local max over 13 keys (12 IMNMX)
        unsigned m = max(key[0], key[1]);
        m = max(m, max(key[2],  key[3]));
        m = max(m, max(key[4],  key[5]));
        m = max(m, max(key[6],  key[7]));
        m = max(m, max(key[8],  key[9]));
        m = max(m, max(key[10], key[11]));
        m = max(m, key[12]);

        // one REDUX serves both halves (disjoint masks)
        const unsigned w = __reduce_max_sync(gmask, m);
        const int bi = (int)((~w) & 0xFFu);
        bis[it] = bi;

        if (it < 3) {
            const uint4 t = __ldg(reinterpret_cast<const uint4*>(g_tbl.w[bi][q]));
            const unsigned tw[3] = {t.x, t.y, t.z};
#pragma unroll
            for (int s = 0; s < 3; ++s)
#pragma unroll
                for (int c = 0; c < 4; ++c) {
                    const unsigned mm = __byte_perm(tw[s], 0u, 0x1111 * c);
                    key[4 * s + c] &= (~mm | 0xFFu);   // fused to one LOP3
                }
            const unsigned m12 = __byte_perm(t.w, 0u, 0x0000);
            key[12] &= (~m12 | 0xFFu);
        }
    }

    // ---- per-half scalar tail (computed once per lane, covers its item) ----
    int px[4], py[4], pk[4];
#pragma unroll
    for (int t = 0; t < 4; ++t) {
        const int x = (int)__umulhi((unsigned)bis[t], MUL14);     // bi / 14
        const int y = bis[t] - 14 * x;
        px[t] = x; py[t] = y; pk[t] = x | (y << 4);
    }

    unsigned kbest = 0;
    {
        const int pa[6] = {0, 0, 0, 1, 1, 2};
        const int pb[6] = {1, 2, 3, 2, 3, 3};
#pragma unroll
        for (int qq = 0; qq < 6; ++qq) {
            const int dx = px[pb[qq]] - px[pa[qq]];
            const int dy = py[pb[qq]] - py[pa[qq]];
            const int d  = dx * dx + dy * dy;       // <= 338
            const unsigned kd = ((unsigned)d << 20) | ((unsigned)(5 - qq) << 16)
                              | (unsigned)(pk[pa[qq]] | (pk[pb[qq]] << 8));
            kbest = (kbest > kd) ? kbest : kd;
        }
    }
    const int ax = (int)(kbest & 0xFu);
    const int ay = (int)((kbest >> 4)  & 0xFu);
    const int bx = (int)((kbest >> 8)  & 0xFu);
    const int by = (int)((kbest >> 12) & 0xFu);

    // d1 - d2 = Cy*i + Cg*eu + mCc   (ev = i - 14*eu folded in)
    const int dxc = bx - ax, dyc = by - ay;
    const int Cy  = 2 * dyc;
    const int Cg  = 2 * dxc - 14 * Cy;
    const int mCc = -(dxc * (ax + bx) + dyc * (ay + by));

    float4* __restrict__ o1 = out + (size_t)item * NVEC;
    float4* __restrict__ o2 = o1 + (size_t)B * NVEC;

#pragma unroll
    for (int s = 0; s < 3; ++s) {
        float r1[4], r2[4];
#pragma unroll
        for (int c = 0; c < 4; ++c) {
            const int i  = 4 * q + 64 * s + c;
            const int eu = (int)__umulhi((unsigned)i, MUL14);        // i / 14
            const int pv = Cy * i + (Cg * eu + mCc);                 // 2x IMAD
            const unsigned m1b = ((unsigned)pv >> 31) * 0x3F800000u; // SHF + IMAD
            r1[c] = __uint_as_float(m1b);       // 1.0f if d1<d2 else 0.0f
            r2[c] = 1.0f - r1[c];               // FADD, exact on {0,1}
        }
        __stwt(o1 + q + 16 * s, make_float4(r1[0], r1[1], r1[2], r1[3]));
        __stwt(o2 + q + 16 * s, make_float4(r2[0], r2[1], r2[2], r2[3]));
    }
    if (q < 4) {                                 // elems 192..195, scalar
        const int i  = 192 + q;                  // eu = 13
        const int pv = Cy * i + (Cg * 13 + mCc);
        const unsigned m1b = ((unsigned)pv >> 31) * 0x3F800000u;
        const float r1 = __uint_as_float(m1b);
        __stwt(reinterpret_cast<float*>(o1) + i, r1);
        __stwt(reinterpret_cast<float*>(o2) + i, 1.0f - r1);
    }
}

extern "C" void kernel_launch(void* const* d_in, const int* in_sizes, int n_in,
                              void* d_out, int out_size)
{
    const float4* hm  = (const float4*)d_in[0];
    float4*       out = (float4*)d_out;
    const int B = in_sizes[0] / NPIX;              // 131072
    const int nwarps = (B + 1) / 2;                // 2 items per warp
    const int grid = (nwarps + WPB - 1) / WPB;     // 8192
    nms_masks_kernel<<<grid, THREADS>>>(hm, out, B);
}